// round 12
// baseline (speedup 1.0000x reference)
#include <cuda_runtime.h>
#include <cuda_fp16.h>
#include <math.h>
#include <cstdint>

// Problem constants (fixed by the dataset)
constexpr int Bn = 4096, Tn = 32, Xn = 256, Hn = 256, Zn = 256, Gn = 128, Yn = 2;
constexpr int BT = Bn * Tn; // 131072

#define DI __device__ __forceinline__

DI uint32_t smem_u32(const void* p) {
    uint32_t a;
    asm("{ .reg .u64 t; cvta.to.shared.u64 t, %1; cvt.u32.u64 %0, t; }" : "=r"(a) : "l"(p));
    return a;
}
DI float sigf(float x) { return 1.0f / (1.0f + expf(-x)); }

DI void ldm_x4(uint32_t r[4], uint32_t addr) {
    asm volatile("ldmatrix.sync.aligned.m8n8.x4.shared.b16 {%0,%1,%2,%3}, [%4];"
                 : "=r"(r[0]), "=r"(r[1]), "=r"(r[2]), "=r"(r[3]) : "r"(addr));
}
DI void mma_f16(float d[4], const uint32_t a[4], const uint32_t b[2]) {
    asm volatile(
        "mma.sync.aligned.m16n8k16.row.col.f32.f16.f16.f32 "
        "{%0,%1,%2,%3}, {%4,%5,%6,%7}, {%8,%9}, {%0,%1,%2,%3};"
        : "+f"(d[0]), "+f"(d[1]), "+f"(d[2]), "+f"(d[3])
        : "r"(a[0]), "r"(a[1]), "r"(a[2]), "r"(a[3]), "r"(b[0]), "r"(b[1]));
}
DI void cp16(uint32_t dst, const void* src) {
    asm volatile("cp.async.cg.shared.global [%0], [%1], 16;" :: "r"(dst), "l"(src));
}
#define CP_COMMIT() asm volatile("cp.async.commit_group;" ::: "memory")
#define CP_WAIT(n)  asm volatile("cp.async.wait_group %0;" :: "n"(n) : "memory")

// write fp32 value as fp16 hi/lo pair into a slab [row][512] = [hi(256)|lo(256)]
DI void slab_write(__half* slab, size_t row, int col, float v) {
    __half h = __float2half_rn(v);
    slab[row * 512 + col]       = h;
    slab[row * 512 + 256 + col] = __float2half_rn(v - __half2float(h));
}

// ============================ static device scratch ============================
__device__ float g_U  [4096 * 256];
__device__ float g_HD [4096 * 1024];            // [mu_p | lp | mu_q | lq]
__device__ float g_Hf [2 * 4096 * 256];         // f32 h state (prev/next)
__device__ float g_G  [131072 * 128];
// fp16 hi/lo slabs: [row][512] = [hi|lo]
__device__ __align__(16) __half g_Xs  [(size_t)131072 * 512];
__device__ __align__(16) __half g_Hseq[(size_t)131072 * 512];
__device__ __align__(16) __half g_Zseq[(size_t)131072 * 512];
__device__ __align__(16) __half g_Hst [2 * 4096 * 512];
__device__ __align__(16) __half g_Zst [2 * 4096 * 512];
__device__ __align__(16) __half g_RH  [4096 * 512];
__device__ __align__(16) __half g_HZP [4096 * 512];
__device__ __align__(16) __half g_HZQ [4096 * 512];
// prepacked weights: fp16 hi only, transposed, [N][K] K-major (full fan-in K)
constexpr size_t O2 = 0;                   // gates  [512][768]  (Wr|Wu full)
constexpr size_t O3 = O2 + 512 * 768;      // cand   [256][768]  (Wh full)
constexpr size_t O4 = O3 + 256 * 768;      // latent [512][512]  (Wzp|Wzq x,h-part)
constexpr size_t O5 = O4 + 512 * 512;      // heads  [1024][256]
constexpr size_t O6 = O5 + 1024 * 256;     // g      [128][768]
constexpr size_t WTOT = O6 + 128 * 768;
__device__ __align__(16) __half g_Wp[WTOT];

// ============================ A descriptor: up to 3 slabs with row strides ====
struct ADesc {
    const __half* p0[3]; int st0[3];
    const __half* p1[3]; int st1[3];
};

// ============================ Epilogues ============================
struct EP_RU { // r -> RH slab (r*h_prev), u -> f32 U
    const float* br_; const float* bu_; const float* hpf; float* U; __half* RH;
    DI void operator()(int b, int col, float acc) const {
        if (col < 256) {
            float r = sigf(acc + br_[col]);
            slab_write(RH, b, col, r * hpf[b * 256 + col]);
        } else {
            U[b * 256 + col - 256] = sigf(acc + bu_[col - 256]);
        }
    }
};
struct EP_H {
    const float* bh_; const float* U; const float* hpf; float* hnf;
    __half* Hst; __half* Hseq; int t;
    DI void operator()(int b, int c, float acc) const {
        size_t bt = (size_t)b * Tn + t;
        float ht = tanhf(acc + bh_[c]);
        float u  = U[b * 256 + c];
        float h  = (1.0f - u) * hpf[b * 256 + c] + u * ht;
        hnf[b * 256 + c] = h;
        slab_write(Hst, b, c, h);
        slab_write(Hseq, bt, c, h);
    }
};
struct EP_ZPQ {
    const float* bzp_; const float* bzq_; const float* yph; const float* WzqY;
    __half* P; __half* Q; int t;
    DI void operator()(int b, int col, float acc) const {
        if (col < 256) {
            slab_write(P, b, col, tanhf(acc + bzp_[col]));
        } else {
            int c = col - 256;
            size_t yi = ((size_t)b * Tn + t) * 2;
            float v = acc + bzq_[c] + yph[yi] * WzqY[c] + yph[yi + 1] * WzqY[256 + c];
            slab_write(Q, b, c, tanhf(v));
        }
    }
};
struct EP_HEADS {
    float* HD; const float* bias[4];
    DI void operator()(int b, int col, float acc) const {
        int seg = col >> 8, c = col & 255;
        HD[(size_t)b * 1024 + col] = acc + bias[seg][c];
    }
};
struct EP_G {
    float* G; const float* bg;
    DI void operator()(int row, int col, float acc) const {
        G[(size_t)row * 128 + col] = tanhf(acc + bg[col]);
    }
};

// ============================ fp16 2-term split mma.sync GEMM ============================
// R7 proven config: CTA tile 64xBN (BN=128 or 64). BK=32 fp16; K' = 2K.
// BN=128: 8 warps 2(m)x4(n), warp 32x32. BN=64: 8 warps 4(m)x2(n), warp 16x32.
// SMEM: 6 stages x (A 64x80B + B BNx80B), cp.async pipeline.
template <int BN, class EP>
__global__ __launch_bounds__(256, 2)
void tgemm(ADesc ad, EP ep, const __half* __restrict__ Bp, int K) {
    constexpr int WN_ = (BN == 128) ? 4 : 2;
    constexpr int WM_ = 8 / WN_;
    constexpr int WTM = 64 / WM_;
    constexpr int WTN = BN / WN_;
    constexpr int MF  = WTM / 16;
    constexpr int NF  = WTN / 8;
    constexpr int NB  = WTN / 16;
    constexpr int A_T = 64 * 80;
    constexpr int B_T = BN * 80;
    constexpr int STG = A_T + B_T;
    constexpr int NSTG = 6;

    extern __shared__ __align__(16) uint8_t smem[];
    const uint32_t sb = smem_u32(smem);

    const int tid  = threadIdx.x;
    const int lane = tid & 31;
    const int warp = tid >> 5;
    const int m0 = blockIdx.y * 64;
    const int n0 = blockIdx.x * BN;
    const int nseg = n0 >> 8;
    const int warpM = (warp / WN_) * WTM;
    const int warpN = (warp % WN_) * WTN;
    const int cpt = K >> 5;
    const int nch = 2 * cpt;

    const __half* const* pp = (nseg < 2) ? ad.p0 : ad.p1;
    const int* st            = (nseg < 2) ? ad.st0 : ad.st1;

    float acc[MF][NF][4];
#pragma unroll
    for (int i = 0; i < MF; i++)
#pragma unroll
        for (int j = 0; j < NF; j++)
#pragma unroll
            for (int q = 0; q < 4; q++) acc[i][j][q] = 0.0f;

    auto fill = [&](int ch, int stg) {
        int term = ch >= cpt;
        int chk = term ? ch - cpt : ch;
        { // A: 64 rows x 64B = 256 x 16B chunks
            int row = tid >> 2, q = tid & 3;
            int kk = chk * 32 + q * 8;
            int slab = kk >> 8, o = kk & 255;
            const __half* src = pp[slab] + (size_t)(m0 + row) * st[slab] + term * 256 + o;
            cp16(sb + stg * STG + row * 80 + q * 16, src);
        }
        // B: BN rows x 64B
#pragma unroll
        for (int c = 0; c < BN / 64; c++) {
            int id = c * 256 + tid;
            int row = id >> 2, q = id & 3;
            const __half* bs = Bp + (size_t)(n0 + row) * K + chk * 32 + q * 8;
            cp16(sb + stg * STG + A_T + row * 80 + q * 16, bs);
        }
    };

    auto mmastep = [&](int stg) {
        const uint32_t Ab = sb + stg * STG;
        const uint32_t Bb = Ab + A_T;
#pragma unroll
        for (int ks = 0; ks < 2; ks++) {
            uint32_t afr[MF][4];
#pragma unroll
            for (int mf = 0; mf < MF; mf++)
                ldm_x4(afr[mf], Ab + (warpM + mf * 16 + (lane & 15)) * 80
                                   + ((ks << 1) + (lane >> 4)) * 16);
            uint32_t bfr[NB][4];
#pragma unroll
            for (int j = 0; j < NB; j++)
                ldm_x4(bfr[j], Bb + (warpN + j * 16 + (lane & 7) + ((lane >> 4) & 1) * 8) * 80
                                  + ((ks << 1) + ((lane >> 3) & 1)) * 16);
#pragma unroll
            for (int mf = 0; mf < MF; mf++)
#pragma unroll
                for (int nf = 0; nf < NF; nf++)
                    mma_f16(acc[mf][nf], afr[mf], &bfr[nf >> 1][(nf & 1) * 2]);
        }
    };

    // prologue: NSTG-1 = 5 chunks in flight
#pragma unroll
    for (int ch = 0; ch < NSTG - 1; ch++) {
        if (ch < nch) fill(ch, ch);
        CP_COMMIT();
    }

    for (int i = 0; i < nch; i++) {
        CP_WAIT(NSTG - 2);
        __syncthreads();
        if (i + NSTG - 1 < nch) fill(i + NSTG - 1, (i + NSTG - 1) % NSTG);
        CP_COMMIT();
        mmastep(i % NSTG);
    }

    // register-direct fused epilogue (mma.m16n8k16 C fragment mapping)
#pragma unroll
    for (int mf = 0; mf < MF; mf++)
#pragma unroll
        for (int nf = 0; nf < NF; nf++)
#pragma unroll
            for (int j = 0; j < 4; j++) {
                int m = m0 + warpM + mf * 16 + (lane >> 2) + ((j >> 1) << 3);
                int n = n0 + warpN + (nf >> 1) * 16 + (nf & 1) * 8 + ((lane & 3) << 1) + (j & 1);
                ep(m, n, acc[mf][nf][j]);
            }
}
constexpr int SMEM128 = 6 * (64 + 128) * 80;   // 92160
constexpr int SMEM64  = 6 * (64 + 64) * 80;    // 61440

// ============================ fused weight prep ============================
struct PrepSrc { const float* w[10]; }; // Wr,Wu,Wh,Wzp,Wzq,Wpm,Wps,Wqm,Wqs,Wg

constexpr int PREP_TOT = 1212416;

__global__ void prep_all(PrepSrc ps, __half* __restrict__ dst) {
    // slice table: srcIdx, src_ld, src_row0, dst_off, dst_row0, Kdst, N
    struct S { int si, sld, sr0; size_t doff; int dr0, K, N; };
    const S tab[10] = {
        {0, 256, 0, O2,   0, 768, 256},   // Wr full  -> gates rows 0-255
        {1, 256, 0, O2, 256, 768, 256},   // Wu full  -> gates rows 256-511
        {2, 256, 0, O3,   0, 768, 256},   // Wh full  -> cand
        {3, 256, 0, O4,   0, 512, 256},   // Wzp full -> latent rows 0-255
        {4, 256, 0, O4, 256, 512, 256},   // Wzq x,h  -> latent rows 256-511
        {5, 256, 0, O5,   0, 256, 256},   // Wpm
        {6, 256, 0, O5, 256, 256, 256},   // Wps
        {7, 256, 0, O5, 512, 256, 256},   // Wqm
        {8, 256, 0, O5, 768, 256, 256},   // Wqs
        {9, 128, 0, O6,   0, 768, 128},   // Wg
    };
    const int cnt[10] = {196608, 196608, 196608, 131072, 131072,
                         65536, 65536, 65536, 65536, 98304};
    int e = blockIdx.x * 256 + threadIdx.x;
    if (e >= PREP_TOT) return;
    int s = 9;
    int base = 0;
#pragma unroll
    for (int i = 0; i < 10; i++) {
        int nb = base + cnt[i];
        if (e < nb) { s = i; break; }
        base = nb;
    }
    const S& t = tab[s];
    int local = e - base;
    int k = local / t.N, n = local % t.N;
    float v = ps.w[t.si][(size_t)(t.sr0 + k) * t.sld + n];
    dst[t.doff + (size_t)(t.dr0 + n) * t.K + k] = __float2half_rn(v);
}

// ============================ small kernels ============================
__global__ void init_copy(const float* __restrict__ x, const float* __restrict__ h0,
                          const float* __restrict__ z0, __half* __restrict__ Xs,
                          float* __restrict__ Hf, __half* __restrict__ Hst,
                          __half* __restrict__ Zst) {
    size_t idx = (size_t)blockIdx.x * blockDim.x + threadIdx.x;
    size_t r = idx >> 8;
    int k = (int)(idx & 255);
    slab_write(Xs, r, k, x[idx]);
    if (idx < (size_t)Bn * Hn) {
        float hv = h0[idx], zv = z0[idx];
        Hf[idx] = hv;
        slab_write(Hst, r, k, hv);
        slab_write(Zst, r, k, zv);
    }
}

__global__ void step_latent(const float* __restrict__ HD, const float* __restrict__ eps_t,
                            __half* __restrict__ Zst, __half* __restrict__ Zseq,
                            float* __restrict__ outKL, int t) {
    int b = blockIdx.x, c = threadIdx.x;
    size_t hb = (size_t)b * 1024;
    float mup = HD[hb + c];
    float lp  = HD[hb + 256 + c];
    float muq = HD[hb + 512 + c];
    float lq  = HD[hb + 768 + c];
    float z = muq + expf(0.5f * lq) * eps_t[b * 256 + c];
    size_t bt = (size_t)b * Tn + t;
    slab_write(Zst, b, c, z);
    slab_write(Zseq, bt, c, z);
    float d = muq - mup;
    float kl = 0.5f * (lp - lq) + (expf(lq) + d * d) / (2.0f * expf(lp)) - 0.5f;

    __shared__ float red[8];
    for (int o = 16; o; o >>= 1) kl += __shfl_down_sync(0xffffffffu, kl, o);
    if ((threadIdx.x & 31) == 0) red[threadIdx.x >> 5] = kl;
    __syncthreads();
    if (threadIdx.x == 0) {
        float s = 0.0f;
#pragma unroll
        for (int i = 0; i < 8; i++) s += red[i];
        outKL[bt] = s;
    }
}

__global__ void yhead(const float* __restrict__ G, const float* __restrict__ Wy,
                      const float* __restrict__ by, float* __restrict__ outY) {
    int r = blockIdx.x * 8 + (threadIdx.x >> 5);
    int lane = threadIdx.x & 31;
    float s0 = 0.0f, s1 = 0.0f;
    const float* g = G + (size_t)r * 128;
    for (int k = lane; k < 128; k += 32) {
        float gv = g[k];
        s0 += gv * Wy[k * 2];
        s1 += gv * Wy[k * 2 + 1];
    }
    for (int o = 16; o; o >>= 1) {
        s0 += __shfl_down_sync(0xffffffffu, s0, o);
        s1 += __shfl_down_sync(0xffffffffu, s1, o);
    }
    if (lane == 0) {
        float l0 = s0 + by[0], l1 = s1 + by[1];
        float m = fmaxf(l0, l1);
        float e0 = expf(l0 - m), e1 = expf(l1 - m);
        float inv = 1.0f / (e0 + e1);
        outY[(size_t)r * 2]     = e0 * inv;
        outY[(size_t)r * 2 + 1] = e1 * inv;
    }
}

__global__ void gatherGT(const float* __restrict__ G, const int* __restrict__ Tph,
                         float* __restrict__ outGT) {
    int b = blockIdx.x;
    int t = Tph[b] - 1;
    outGT[(size_t)b * Gn + threadIdx.x] = G[((size_t)b * Tn + t) * Gn + threadIdx.x];
}

// ============================ launch ============================
extern "C" void kernel_launch(void* const* d_in, const int* in_sizes, int n_in,
                              void* d_out, int out_size) {
    const float* x   = (const float*)d_in[0];
    const float* yph = (const float*)d_in[1];
    const int*   Tph = (const int*)  d_in[2];
    const float* h0  = (const float*)d_in[3];
    const float* z0  = (const float*)d_in[4];
    const float* eps = (const float*)d_in[5];
    const float* Wr  = (const float*)d_in[6];  const float* br  = (const float*)d_in[7];
    const float* Wu  = (const float*)d_in[8];  const float* bu  = (const float*)d_in[9];
    const float* Wh  = (const float*)d_in[10]; const float* bh  = (const float*)d_in[11];
    const float* Wzp = (const float*)d_in[12]; const float* bzp = (const float*)d_in[13];
    const float* Wpm = (const float*)d_in[14]; const float* bpm = (const float*)d_in[15];
    const float* Wps = (const float*)d_in[16]; const float* bps = (const float*)d_in[17];
    const float* Wzq = (const float*)d_in[18]; const float* bzq = (const float*)d_in[19];
    const float* Wqm = (const float*)d_in[20]; const float* bqm = (const float*)d_in[21];
    const float* Wqs = (const float*)d_in[22]; const float* bqs = (const float*)d_in[23];
    const float* Wg  = (const float*)d_in[24]; const float* bg  = (const float*)d_in[25];
    const float* Wy  = (const float*)d_in[26]; const float* by  = (const float*)d_in[27];

    float *U, *HD, *Hf, *Gb;
    __half *Xs, *Hseq, *Zseq, *Hst, *Zst, *RH, *HZP, *HZQ, *Wp;
    {
        void* p;
        cudaGetSymbolAddress(&p, g_U);    U    = (float*)p;
        cudaGetSymbolAddress(&p, g_HD);   HD   = (float*)p;
        cudaGetSymbolAddress(&p, g_Hf);   Hf   = (float*)p;
        cudaGetSymbolAddress(&p, g_G);    Gb   = (float*)p;
        cudaGetSymbolAddress(&p, g_Xs);   Xs   = (__half*)p;
        cudaGetSymbolAddress(&p, g_Hseq); Hseq = (__half*)p;
        cudaGetSymbolAddress(&p, g_Zseq); Zseq = (__half*)p;
        cudaGetSymbolAddress(&p, g_Hst);  Hst  = (__half*)p;
        cudaGetSymbolAddress(&p, g_Zst);  Zst  = (__half*)p;
        cudaGetSymbolAddress(&p, g_RH);   RH   = (__half*)p;
        cudaGetSymbolAddress(&p, g_HZP);  HZP  = (__half*)p;
        cudaGetSymbolAddress(&p, g_HZQ);  HZQ  = (__half*)p;
        cudaGetSymbolAddress(&p, g_Wp);   Wp   = (__half*)p;
    }

    cudaFuncSetAttribute((const void*)tgemm<128, EP_RU>,    cudaFuncAttributeMaxDynamicSharedMemorySize, SMEM128);
    cudaFuncSetAttribute((const void*)tgemm<64,  EP_H>,     cudaFuncAttributeMaxDynamicSharedMemorySize, SMEM64);
    cudaFuncSetAttribute((const void*)tgemm<128, EP_ZPQ>,   cudaFuncAttributeMaxDynamicSharedMemorySize, SMEM128);
    cudaFuncSetAttribute((const void*)tgemm<128, EP_HEADS>, cudaFuncAttributeMaxDynamicSharedMemorySize, SMEM128);
    cudaFuncSetAttribute((const void*)tgemm<128, EP_G>,     cudaFuncAttributeMaxDynamicSharedMemorySize, SMEM128);

    float* out   = (float*)d_out;
    float* outY  = out;
    float* outKL = out + (size_t)BT * Yn;
    float* outGT = out + (size_t)BT * Yn + BT;

    // ---- single fused weight prep ----
    {
        PrepSrc ps;
        ps.w[0] = Wr; ps.w[1] = Wu; ps.w[2] = Wh; ps.w[3] = Wzp; ps.w[4] = Wzq;
        ps.w[5] = Wpm; ps.w[6] = Wps; ps.w[7] = Wqm; ps.w[8] = Wqs; ps.w[9] = Wg;
        prep_all<<<(PREP_TOT + 255) / 256, 256>>>(ps, Wp);
    }

    init_copy<<<BT, 256>>>(x, h0, z0, Xs, Hf, Hst, Zst);

    dim3 blk(256);
    const int XSTRIDE = Tn * 512;   // x slab row stride for per-step addressing

    // phase 2: sequential scan (x folded into K — no AX buffer, no phase-1 GEMM)
    for (int t = 0; t < Tn; t++) {
        int cur = t & 1, nxt = cur ^ 1;
        const float* hpf = Hf + (size_t)cur * Bn * Hn;
        float* hnf       = Hf + (size_t)nxt * Bn * Hn;
        __half* HstC = Hst + (size_t)cur * Bn * 512;
        __half* HstN = Hst + (size_t)nxt * Bn * 512;
        __half* ZstC = Zst + (size_t)cur * Bn * 512;
        __half* ZstN = Zst + (size_t)nxt * Bn * 512;
        const __half* Xt = Xs + (size_t)t * 512;

        { // gates r,u: A = [x_t | h_prev | z_prev], N=512, K=768
            ADesc ad{};
            ad.p0[0] = Xt;   ad.st0[0] = XSTRIDE;
            ad.p0[1] = HstC; ad.st0[1] = 512;
            ad.p0[2] = ZstC; ad.st0[2] = 512;
            for (int i = 0; i < 3; i++) { ad.p1[i] = ad.p0[i]; ad.st1[i] = ad.st0[i]; }
            EP_RU ep{br, bu, hpf, U, RH};
            tgemm<128><<<dim3(512 / 128, Bn / 64), blk, SMEM128>>>(ad, ep, Wp + O2, 768);
        }
        { // candidate + GRU: A = [x_t | r*h_prev | z_prev], N=256, K=768
            ADesc ad{};
            ad.p0[0] = Xt;   ad.st0[0] = XSTRIDE;
            ad.p0[1] = RH;   ad.st0[1] = 512;
            ad.p0[2] = ZstC; ad.st0[2] = 512;
            for (int i = 0; i < 3; i++) { ad.p1[i] = ad.p0[i]; ad.st1[i] = ad.st0[i]; }
            EP_H ep{bh, U, hpf, hnf, HstN, Hseq, t};
            tgemm<64><<<dim3(256 / 64, Bn / 64), blk, SMEM64>>>(ad, ep, Wp + O3, 768);
        }
        { // latent hiddens: A = [x_t | h_new], N=512 (zp|zq), K=512
            ADesc ad{};
            ad.p0[0] = Xt;   ad.st0[0] = XSTRIDE;
            ad.p0[1] = HstN; ad.st0[1] = 512;
            for (int i = 0; i < 3; i++) { ad.p1[i] = ad.p0[i]; ad.st1[i] = ad.st0[i]; }
            EP_ZPQ ep{bzp, bzq, yph, Wzq + 512 * 256, HZP, HZQ, t};
            tgemm<128><<<dim3(512 / 128, Bn / 64), blk, SMEM128>>>(ad, ep, Wp + O4, 512);
        }
        { // heads: N=1024, K=256; A = HZP segs 0-1, HZQ segs 2-3
            ADesc ad{};
            ad.p0[0] = HZP; ad.st0[0] = 512;
            ad.p1[0] = HZQ; ad.st1[0] = 512;
            EP_HEADS ep;
            ep.HD = HD;
            ep.bias[0] = bpm; ep.bias[1] = bps; ep.bias[2] = bqm; ep.bias[3] = bqs;
            tgemm<128><<<dim3(1024 / 128, Bn / 64), blk, SMEM128>>>(ad, ep, Wp + O5, 256);
        }
        step_latent<<<Bn, 256>>>(HD, eps + (size_t)t * Bn * Zn, ZstN, Zseq, outKL, t);
    }

    // phase 3: g = tanh([x|h|z] @ Wg + bg), N=128, K=768 (rows = bt)
    {
        ADesc ad{};
        ad.p0[0] = Xs;   ad.st0[0] = 512;
        ad.p0[1] = Hseq; ad.st0[1] = 512;
        ad.p0[2] = Zseq; ad.st0[2] = 512;
        for (int i = 0; i < 3; i++) { ad.p1[i] = ad.p0[i]; ad.st1[i] = ad.st0[i]; }
        EP_G ep{Gb, bg};
        tgemm<128><<<dim3(Gn / 128, BT / 64), blk, SMEM128>>>(ad, ep, Wp + O6, 768);
    }
    yhead<<<BT / 8, 256>>>(Gb, Wy, by, outY);
    gatherGT<<<Bn, Gn>>>(Gb, Tph, outGT);
}

// round 13
// speedup vs baseline: 1.4795x; 1.4795x over previous
#include <cuda_runtime.h>
#include <cuda_fp16.h>
#include <math.h>
#include <cstdint>

// Problem constants (fixed by the dataset)
constexpr int Bn = 4096, Tn = 32, Xn = 256, Hn = 256, Zn = 256, Gn = 128, Yn = 2;
constexpr int BT = Bn * Tn; // 131072

#define DI __device__ __forceinline__

DI uint32_t smem_u32(const void* p) {
    uint32_t a;
    asm("{ .reg .u64 t; cvta.to.shared.u64 t, %1; cvt.u32.u64 %0, t; }" : "=r"(a) : "l"(p));
    return a;
}
DI float sigf(float x) { return 1.0f / (1.0f + expf(-x)); }

DI void ldm_x4(uint32_t r[4], uint32_t addr) {
    asm volatile("ldmatrix.sync.aligned.m8n8.x4.shared.b16 {%0,%1,%2,%3}, [%4];"
                 : "=r"(r[0]), "=r"(r[1]), "=r"(r[2]), "=r"(r[3]) : "r"(addr));
}
DI void mma_f16(float d[4], const uint32_t a[4], const uint32_t b[2]) {
    asm volatile(
        "mma.sync.aligned.m16n8k16.row.col.f32.f16.f16.f32 "
        "{%0,%1,%2,%3}, {%4,%5,%6,%7}, {%8,%9}, {%0,%1,%2,%3};"
        : "+f"(d[0]), "+f"(d[1]), "+f"(d[2]), "+f"(d[3])
        : "r"(a[0]), "r"(a[1]), "r"(a[2]), "r"(a[3]), "r"(b[0]), "r"(b[1]));
}
DI void cp16(uint32_t dst, const void* src) {
    asm volatile("cp.async.cg.shared.global [%0], [%1], 16;" :: "r"(dst), "l"(src));
}
#define CP_COMMIT() asm volatile("cp.async.commit_group;" ::: "memory")
#define CP_WAIT(n)  asm volatile("cp.async.wait_group %0;" :: "n"(n) : "memory")

// write fp32 value as fp16 hi/lo pair into a slab [row][512] = [hi(256)|lo(256)]
DI void slab_write(__half* slab, size_t row, int col, float v) {
    __half h = __float2half_rn(v);
    slab[row * 512 + col]       = h;
    slab[row * 512 + 256 + col] = __float2half_rn(v - __half2float(h));
}

// ============================ static device scratch ============================
// AX t-major [t][4096][1024]: segs r,u,h,zq (x-projections + biases + y-term)
__device__ float g_AX [(size_t)131072 * 1024];
__device__ float g_U  [4096 * 256];
__device__ float g_Hf [2 * 4096 * 256];          // f32 h state (prev/next)
__device__ float g_MUQ[(size_t)131072 * 256];    // posterior mean per (bt,c)
__device__ float g_LQ [(size_t)131072 * 256];    // posterior log-var per (bt,c)
__device__ float g_G  [131072 * 128];
// fp16 hi/lo slabs: [row][512] = [hi|lo]
__device__ __align__(16) __half g_Xs   [(size_t)131072 * 512];
__device__ __align__(16) __half g_Hseq [(size_t)131072 * 512];
__device__ __align__(16) __half g_Zseq [(size_t)131072 * 512];
__device__ __align__(16) __half g_HZPsq[(size_t)131072 * 512];
__device__ __align__(16) __half g_Hst [2 * 4096 * 512];
__device__ __align__(16) __half g_Zst [2 * 4096 * 512];
__device__ __align__(16) __half g_RH  [4096 * 512];
__device__ __align__(16) __half g_HZQ [4096 * 512];
// prepacked weights fp16, transposed [N][K] K-major
constexpr size_t OAX = 0;                    // [1024][256] x-parts r,u,h,zq
constexpr size_t O2  = OAX + 1024 * 256;     // gates  [512][512] (h|z of Wr,Wu)
constexpr size_t O3  = O2  + 512 * 512;      // cand   [256][512] (h|z of Wh)
constexpr size_t O4q = O3  + 256 * 512;      // latent_q [256][256] (h-part Wzq)
constexpr size_t O4p = O4q + 256 * 256;      // latent_p [256][512] (x|h Wzp)
constexpr size_t O5q = O4p + 256 * 512;      // head_q [512][256] interleaved Wqm/Wqs
constexpr size_t O5p = O5q + 512 * 256;      // head_p [512][256] interleaved Wpm/Wps
constexpr size_t O6  = O5p + 512 * 256;      // g [128][768]
constexpr size_t WTOT = O6 + 128 * 768;
__device__ __align__(16) __half g_Wp[WTOT];

// ============================ A descriptor: up to 3 slabs (stride 512) ========
struct ADesc { const __half* s[3]; };

// ============================ Epilogues (pair interface: cols n, n+1) =========
struct EP_AX { // row = bt; store t-major into AX[1024]
    float* AX; const float* bias[4]; const float* yph; const float* WzqY;
    DI void operator()(int row, int n, float v0, float v1) const {
        int seg = n >> 8, c = n & 255;
        float f0 = v0 + bias[seg][c];
        float f1 = v1 + bias[seg][c + 1];
        if (seg == 3) {
            float y0 = yph[(size_t)row * 2], y1 = yph[(size_t)row * 2 + 1];
            f0 += y0 * WzqY[c]     + y1 * WzqY[256 + c];
            f1 += y0 * WzqY[c + 1] + y1 * WzqY[256 + c + 1];
        }
        size_t base = ((size_t)(row & 31) * Bn + (row >> 5)) * 1024;
        AX[base + n] = f0;
        AX[base + n + 1] = f1;
    }
};
struct EP_RU {
    const float* AXt; const float* hpf; float* U; __half* RH;
    DI void operator()(int b, int n, float v0, float v1) const {
        float p0 = v0 + AXt[(size_t)b * 1024 + n];
        float p1 = v1 + AXt[(size_t)b * 1024 + n + 1];
        if (n < 256) {
            slab_write(RH, b, n,     sigf(p0) * hpf[b * 256 + n]);
            slab_write(RH, b, n + 1, sigf(p1) * hpf[b * 256 + n + 1]);
        } else {
            U[b * 256 + n - 256] = sigf(p0);
            U[b * 256 + n - 255] = sigf(p1);
        }
    }
};
struct EP_H {
    const float* AXt; const float* U; const float* hpf; float* hnf;
    __half* Hst; __half* Hseq; int t;
    DI void operator()(int b, int n, float v0, float v1) const {
        size_t bt = (size_t)b * Tn + t;
#pragma unroll
        for (int j = 0; j < 2; j++) {
            int c = n + j;
            float v = j ? v1 : v0;
            float ht = tanhf(v + AXt[(size_t)b * 1024 + 512 + c]);
            float u  = U[b * 256 + c];
            float h  = (1.0f - u) * hpf[b * 256 + c] + u * ht;
            hnf[b * 256 + c] = h;
            slab_write(Hst, b, c, h);
            slab_write(Hseq, bt, c, h);
        }
    }
};
struct EP_LQ { // hzq = tanh(h@Wzq_h + AX_zq)
    const float* AXt; __half* HZQ;
    DI void operator()(int b, int n, float v0, float v1) const {
        slab_write(HZQ, b, n,     tanhf(v0 + AXt[(size_t)b * 1024 + 768 + n]));
        slab_write(HZQ, b, n + 1, tanhf(v1 + AXt[(size_t)b * 1024 + 768 + n + 1]));
    }
};
struct EP_QHEAD { // interleaved: col 2c = mu_q[c], col 2c+1 = lq[c]; fused reparam
    const float* bqm; const float* bqs; const float* eps_t;
    __half* ZstN; __half* Zseq; float* MUQ; float* LQ; int t;
    DI void operator()(int b, int n, float v0, float v1) const {
        int c = n >> 1;
        float muq = v0 + bqm[c];
        float lq  = v1 + bqs[c];
        float z = muq + expf(0.5f * lq) * eps_t[b * 256 + c];
        size_t bt = (size_t)b * Tn + t;
        slab_write(ZstN, b, c, z);
        slab_write(Zseq, bt, c, z);
        MUQ[bt * 256 + c] = muq;
        LQ[bt * 256 + c]  = lq;
    }
};
struct EP_LP { // hzp = tanh([x|h]@Wzp + bzp), batched over BT rows
    const float* bzp; __half* HZP;
    DI void operator()(int row, int n, float v0, float v1) const {
        slab_write(HZP, row, n,     tanhf(v0 + bzp[n]));
        slab_write(HZP, row, n + 1, tanhf(v1 + bzp[n + 1]));
    }
};
struct EP_PHEAD { // interleaved mu_p/lp; compute KL element, accumulate
    const float* bpm; const float* bps; const float* MUQ; const float* LQ; float* outKL;
    DI void operator()(int row, int n, float v0, float v1) const {
        int c = n >> 1;
        float mup = v0 + bpm[c];
        float lp  = v1 + bps[c];
        float muq = MUQ[(size_t)row * 256 + c];
        float lq  = LQ [(size_t)row * 256 + c];
        float d = muq - mup;
        float kl = 0.5f * (lp - lq) + (expf(lq) + d * d) / (2.0f * expf(lp)) - 0.5f;
        atomicAdd(&outKL[row], kl);
    }
};
struct EP_G {
    float* G; const float* bg;
    DI void operator()(int row, int n, float v0, float v1) const {
        G[(size_t)row * 128 + n]     = tanhf(v0 + bg[n]);
        G[(size_t)row * 128 + n + 1] = tanhf(v1 + bg[n + 1]);
    }
};

// ============================ fp16 2-term split mma.sync GEMM ============================
// R7 proven config: CTA 64xBN. BN=128: 8 warps 2x4, warp 32x32. BN=64: 4x2, warp 16x32.
// K' = 2K (Ahi·Bhi + Alo·Bhi), 32-K chunks, 6-stage cp.async pipeline.
template <int BN, class EP>
__global__ __launch_bounds__(256, 2)
void tgemm(ADesc ad, EP ep, const __half* __restrict__ Bp, int K) {
    constexpr int WN_ = (BN == 128) ? 4 : 2;
    constexpr int WM_ = 8 / WN_;
    constexpr int WTM = 64 / WM_;
    constexpr int WTN = BN / WN_;
    constexpr int MF  = WTM / 16;
    constexpr int NF  = WTN / 8;
    constexpr int NB  = WTN / 16;
    constexpr int A_T = 64 * 80;
    constexpr int B_T = BN * 80;
    constexpr int STG = A_T + B_T;
    constexpr int NSTG = 6;

    extern __shared__ __align__(16) uint8_t smem[];
    const uint32_t sb = smem_u32(smem);

    const int tid  = threadIdx.x;
    const int lane = tid & 31;
    const int warp = tid >> 5;
    const int m0 = blockIdx.y * 64;
    const int n0 = blockIdx.x * BN;
    const int warpM = (warp / WN_) * WTM;
    const int warpN = (warp % WN_) * WTN;
    const int cpt = K >> 5;
    const int nch = 2 * cpt;

    float acc[MF][NF][4];
#pragma unroll
    for (int i = 0; i < MF; i++)
#pragma unroll
        for (int j = 0; j < NF; j++)
#pragma unroll
            for (int q = 0; q < 4; q++) acc[i][j][q] = 0.0f;

    auto fill = [&](int ch, int stg) {
        int term = ch >= cpt;
        int chk = term ? ch - cpt : ch;
        { // A: 64 rows x 64B
            int row = tid >> 2, q = tid & 3;
            int kk = chk * 32 + q * 8;
            int slab = kk >> 8, o = kk & 255;
            const __half* src = ad.s[slab] + (size_t)(m0 + row) * 512 + term * 256 + o;
            cp16(sb + stg * STG + row * 80 + q * 16, src);
        }
        // B: BN rows x 64B
#pragma unroll
        for (int c = 0; c < BN / 64; c++) {
            int id = c * 256 + tid;
            int row = id >> 2, q = id & 3;
            const __half* bs = Bp + (size_t)(n0 + row) * K + chk * 32 + q * 8;
            cp16(sb + stg * STG + A_T + row * 80 + q * 16, bs);
        }
    };

    auto mmastep = [&](int stg) {
        const uint32_t Ab = sb + stg * STG;
        const uint32_t Bb = Ab + A_T;
#pragma unroll
        for (int ks = 0; ks < 2; ks++) {
            uint32_t afr[MF][4];
#pragma unroll
            for (int mf = 0; mf < MF; mf++)
                ldm_x4(afr[mf], Ab + (warpM + mf * 16 + (lane & 15)) * 80
                                   + ((ks << 1) + (lane >> 4)) * 16);
            uint32_t bfr[NB][4];
#pragma unroll
            for (int j = 0; j < NB; j++)
                ldm_x4(bfr[j], Bb + (warpN + j * 16 + (lane & 7) + ((lane >> 4) & 1) * 8) * 80
                                  + ((ks << 1) + ((lane >> 3) & 1)) * 16);
#pragma unroll
            for (int mf = 0; mf < MF; mf++)
#pragma unroll
                for (int nf = 0; nf < NF; nf++)
                    mma_f16(acc[mf][nf], afr[mf], &bfr[nf >> 1][(nf & 1) * 2]);
        }
    };

#pragma unroll
    for (int ch = 0; ch < NSTG - 1; ch++) {
        if (ch < nch) fill(ch, ch);
        CP_COMMIT();
    }
    for (int i = 0; i < nch; i++) {
        CP_WAIT(NSTG - 2);
        __syncthreads();
        if (i + NSTG - 1 < nch) fill(i + NSTG - 1, (i + NSTG - 1) % NSTG);
        CP_COMMIT();
        mmastep(i % NSTG);
    }

    // pair epilogue: each call covers cols (n, n+1) of one row
#pragma unroll
    for (int mf = 0; mf < MF; mf++)
#pragma unroll
        for (int nf = 0; nf < NF; nf++) {
            int colb = n0 + warpN + (nf >> 1) * 16 + (nf & 1) * 8 + (lane & 3) * 2;
            int row0 = m0 + warpM + mf * 16 + (lane >> 2);
            ep(row0,     colb, acc[mf][nf][0], acc[mf][nf][1]);
            ep(row0 + 8, colb, acc[mf][nf][2], acc[mf][nf][3]);
        }
}
constexpr int SMEM128 = 6 * (64 + 128) * 80;   // 92160
constexpr int SMEM64  = 6 * (64 + 64) * 80;    // 61440

// ============================ fused weight prep ============================
struct PrepSrc { const float* w[10]; }; // Wr,Wu,Wh,Wzp,Wzq,Wpm,Wps,Wqm,Wqs,Wg
constexpr int PREP_TOT = 1212416;

__global__ void prep_all(PrepSrc ps, __half* __restrict__ dst) {
    // srcIdx, src_ld, src_row0, dst_off, rowMul, rowAdd, Kdst, Ncols
    struct S { int si, sld, sr0; size_t doff; int mul, add, K, N; };
    const S tab[14] = {
        {0, 256,   0, OAX, 1,    0, 256, 256},  // Wr x
        {1, 256,   0, OAX, 1,  256, 256, 256},  // Wu x
        {2, 256,   0, OAX, 1,  512, 256, 256},  // Wh x
        {4, 256,   0, OAX, 1,  768, 256, 256},  // Wzq x
        {0, 256, 256, O2,  1,    0, 512, 256},  // Wr h|z
        {1, 256, 256, O2,  1,  256, 512, 256},  // Wu h|z
        {2, 256, 256, O3,  1,    0, 512, 256},  // Wh h|z
        {4, 256, 256, O4q, 1,    0, 256, 256},  // Wzq h
        {3, 256,   0, O4p, 1,    0, 512, 256},  // Wzp x|h
        {7, 256,   0, O5q, 2,    0, 256, 256},  // Wqm (even rows)
        {8, 256,   0, O5q, 2,    1, 256, 256},  // Wqs (odd rows)
        {5, 256,   0, O5p, 2,    0, 256, 256},  // Wpm
        {6, 256,   0, O5p, 2,    1, 256, 256},  // Wps
        {9, 128,   0, O6,  1,    0, 768, 128},  // Wg
    };
    const int cnt[14] = {65536,65536,65536,65536, 131072,131072,131072, 65536,
                         131072, 65536,65536,65536,65536, 98304};
    int e = blockIdx.x * 256 + threadIdx.x;
    if (e >= PREP_TOT) return;
    int s = 13, base = 0;
#pragma unroll
    for (int i = 0; i < 14; i++) {
        int nb = base + cnt[i];
        if (e < nb) { s = i; break; }
        base = nb;
    }
    const S& t = tab[s];
    int local = e - base;
    int k = local / t.N, n = local % t.N;
    float v = ps.w[t.si][(size_t)(t.sr0 + k) * t.sld + n];
    dst[t.doff + (size_t)(t.mul * n + t.add) * t.K + k] = __float2half_rn(v);
}

// ============================ small kernels ============================
__global__ void init_copy(const float* __restrict__ x, const float* __restrict__ h0,
                          const float* __restrict__ z0, __half* __restrict__ Xs,
                          float* __restrict__ Hf, __half* __restrict__ Hst,
                          __half* __restrict__ Zst) {
    size_t idx = (size_t)blockIdx.x * blockDim.x + threadIdx.x;
    size_t r = idx >> 8;
    int k = (int)(idx & 255);
    slab_write(Xs, r, k, x[idx]);
    if (idx < (size_t)Bn * Hn) {
        float hv = h0[idx], zv = z0[idx];
        Hf[idx] = hv;
        slab_write(Hst, r, k, hv);
        slab_write(Zst, r, k, zv);
    }
}

__global__ void yhead(const float* __restrict__ G, const float* __restrict__ Wy,
                      const float* __restrict__ by, float* __restrict__ outY) {
    int r = blockIdx.x * 8 + (threadIdx.x >> 5);
    int lane = threadIdx.x & 31;
    float s0 = 0.0f, s1 = 0.0f;
    const float* g = G + (size_t)r * 128;
    for (int k = lane; k < 128; k += 32) {
        float gv = g[k];
        s0 += gv * Wy[k * 2];
        s1 += gv * Wy[k * 2 + 1];
    }
    for (int o = 16; o; o >>= 1) {
        s0 += __shfl_down_sync(0xffffffffu, s0, o);
        s1 += __shfl_down_sync(0xffffffffu, s1, o);
    }
    if (lane == 0) {
        float l0 = s0 + by[0], l1 = s1 + by[1];
        float m = fmaxf(l0, l1);
        float e0 = expf(l0 - m), e1 = expf(l1 - m);
        float inv = 1.0f / (e0 + e1);
        outY[(size_t)r * 2]     = e0 * inv;
        outY[(size_t)r * 2 + 1] = e1 * inv;
    }
}

__global__ void gatherGT(const float* __restrict__ G, const int* __restrict__ Tph,
                         float* __restrict__ outGT) {
    int b = blockIdx.x;
    int t = Tph[b] - 1;
    outGT[(size_t)b * Gn + threadIdx.x] = G[((size_t)b * Tn + t) * Gn + threadIdx.x];
}

// ============================ launch ============================
extern "C" void kernel_launch(void* const* d_in, const int* in_sizes, int n_in,
                              void* d_out, int out_size) {
    const float* x   = (const float*)d_in[0];
    const float* yph = (const float*)d_in[1];
    const int*   Tph = (const int*)  d_in[2];
    const float* h0  = (const float*)d_in[3];
    const float* z0  = (const float*)d_in[4];
    const float* eps = (const float*)d_in[5];
    const float* Wr  = (const float*)d_in[6];  const float* br  = (const float*)d_in[7];
    const float* Wu  = (const float*)d_in[8];  const float* bu  = (const float*)d_in[9];
    const float* Wh  = (const float*)d_in[10]; const float* bh  = (const float*)d_in[11];
    const float* Wzp = (const float*)d_in[12]; const float* bzp = (const float*)d_in[13];
    const float* Wpm = (const float*)d_in[14]; const float* bpm = (const float*)d_in[15];
    const float* Wps = (const float*)d_in[16]; const float* bps = (const float*)d_in[17];
    const float* Wzq = (const float*)d_in[18]; const float* bzq = (const float*)d_in[19];
    const float* Wqm = (const float*)d_in[20]; const float* bqm = (const float*)d_in[21];
    const float* Wqs = (const float*)d_in[22]; const float* bqs = (const float*)d_in[23];
    const float* Wg  = (const float*)d_in[24]; const float* bg  = (const float*)d_in[25];
    const float* Wy  = (const float*)d_in[26]; const float* by  = (const float*)d_in[27];

    float *AX, *U, *Hf, *MUQ, *LQ, *Gb;
    __half *Xs, *Hseq, *Zseq, *HZPsq, *Hst, *Zst, *RH, *HZQ, *Wp;
    {
        void* p;
        cudaGetSymbolAddress(&p, g_AX);    AX    = (float*)p;
        cudaGetSymbolAddress(&p, g_U);     U     = (float*)p;
        cudaGetSymbolAddress(&p, g_Hf);    Hf    = (float*)p;
        cudaGetSymbolAddress(&p, g_MUQ);   MUQ   = (float*)p;
        cudaGetSymbolAddress(&p, g_LQ);    LQ    = (float*)p;
        cudaGetSymbolAddress(&p, g_G);     Gb    = (float*)p;
        cudaGetSymbolAddress(&p, g_Xs);    Xs    = (__half*)p;
        cudaGetSymbolAddress(&p, g_Hseq);  Hseq  = (__half*)p;
        cudaGetSymbolAddress(&p, g_Zseq);  Zseq  = (__half*)p;
        cudaGetSymbolAddress(&p, g_HZPsq); HZPsq = (__half*)p;
        cudaGetSymbolAddress(&p, g_Hst);   Hst   = (__half*)p;
        cudaGetSymbolAddress(&p, g_Zst);   Zst   = (__half*)p;
        cudaGetSymbolAddress(&p, g_RH);    RH    = (__half*)p;
        cudaGetSymbolAddress(&p, g_HZQ);   HZQ   = (__half*)p;
        cudaGetSymbolAddress(&p, g_Wp);    Wp    = (__half*)p;
    }

    cudaFuncSetAttribute((const void*)tgemm<128, EP_AX>,    cudaFuncAttributeMaxDynamicSharedMemorySize, SMEM128);
    cudaFuncSetAttribute((const void*)tgemm<128, EP_RU>,    cudaFuncAttributeMaxDynamicSharedMemorySize, SMEM128);
    cudaFuncSetAttribute((const void*)tgemm<64,  EP_H>,     cudaFuncAttributeMaxDynamicSharedMemorySize, SMEM64);
    cudaFuncSetAttribute((const void*)tgemm<64,  EP_LQ>,    cudaFuncAttributeMaxDynamicSharedMemorySize, SMEM64);
    cudaFuncSetAttribute((const void*)tgemm<128, EP_QHEAD>, cudaFuncAttributeMaxDynamicSharedMemorySize, SMEM128);
    cudaFuncSetAttribute((const void*)tgemm<128, EP_LP>,    cudaFuncAttributeMaxDynamicSharedMemorySize, SMEM128);
    cudaFuncSetAttribute((const void*)tgemm<128, EP_PHEAD>, cudaFuncAttributeMaxDynamicSharedMemorySize, SMEM128);
    cudaFuncSetAttribute((const void*)tgemm<128, EP_G>,     cudaFuncAttributeMaxDynamicSharedMemorySize, SMEM128);

    float* out   = (float*)d_out;
    float* outY  = out;
    float* outKL = out + (size_t)BT * Yn;
    float* outGT = out + (size_t)BT * Yn + BT;

    // zero KL accumulator (graph-capturable async memset)
    cudaMemsetAsync(outKL, 0, (size_t)BT * sizeof(float));

    // ---- single fused weight prep ----
    {
        PrepSrc ps;
        ps.w[0] = Wr; ps.w[1] = Wu; ps.w[2] = Wh; ps.w[3] = Wzp; ps.w[4] = Wzq;
        ps.w[5] = Wpm; ps.w[6] = Wps; ps.w[7] = Wqm; ps.w[8] = Wqs; ps.w[9] = Wg;
        prep_all<<<(PREP_TOT + 255) / 256, 256>>>(ps, Wp);
    }

    init_copy<<<BT, 256>>>(x, h0, z0, Xs, Hf, Hst, Zst);

    dim3 blk(256);

    // phase 1: x-projections (r,u,h,zq) -> AX t-major, N=1024, K=256
    {
        ADesc ad{}; ad.s[0] = Xs;
        EP_AX ep;
        ep.AX = AX;
        ep.bias[0] = br; ep.bias[1] = bu; ep.bias[2] = bh; ep.bias[3] = bzq;
        ep.yph = yph; ep.WzqY = Wzq + 512 * 256;
        tgemm<128><<<dim3(1024 / 128, BT / 64), blk, SMEM128>>>(ad, ep, Wp + OAX, 256);
    }

    // phase 2: sequential scan — 4 launches/step (posterior chain only)
    for (int t = 0; t < Tn; t++) {
        int cur = t & 1, nxt = cur ^ 1;
        const float* hpf = Hf + (size_t)cur * Bn * Hn;
        float* hnf       = Hf + (size_t)nxt * Bn * Hn;
        __half* HstC = Hst + (size_t)cur * Bn * 512;
        __half* HstN = Hst + (size_t)nxt * Bn * 512;
        __half* ZstC = Zst + (size_t)cur * Bn * 512;
        __half* ZstN = Zst + (size_t)nxt * Bn * 512;
        const float* AXt = AX + (size_t)t * Bn * 1024;

        { // gates r,u: A = [h_prev | z_prev], N=512, K=512
            ADesc ad{}; ad.s[0] = HstC; ad.s[1] = ZstC;
            EP_RU ep{AXt, hpf, U, RH};
            tgemm<128><<<dim3(4, 64), blk, SMEM128>>>(ad, ep, Wp + O2, 512);
        }
        { // candidate + GRU: A = [r*h_prev | z_prev], N=256, K=512
            ADesc ad{}; ad.s[0] = RH; ad.s[1] = ZstC;
            EP_H ep{AXt, U, hpf, hnf, HstN, Hseq, t};
            tgemm<64><<<dim3(4, 64), blk, SMEM64>>>(ad, ep, Wp + O3, 512);
        }
        { // latent_q: A = h_new, N=256, K=256
            ADesc ad{}; ad.s[0] = HstN;
            EP_LQ ep{AXt, HZQ};
            tgemm<64><<<dim3(4, 64), blk, SMEM64>>>(ad, ep, Wp + O4q, 256);
        }
        { // head_q (mu_q|lq interleaved) + fused reparam: N=512, K=256
            ADesc ad{}; ad.s[0] = HZQ;
            EP_QHEAD ep{bqm, bqs, eps + (size_t)t * Bn * Zn, ZstN, Zseq, MUQ, LQ, t};
            tgemm<128><<<dim3(4, 64), blk, SMEM128>>>(ad, ep, Wp + O5q, 256);
        }
    }

    // phase 3a: prior branch batched over BT rows (off critical path)
    { // latent_p: A = [x | h], N=256, K=512
        ADesc ad{}; ad.s[0] = Xs; ad.s[1] = Hseq;
        EP_LP ep{bzp, HZPsq};
        tgemm<128><<<dim3(2, BT / 64), blk, SMEM128>>>(ad, ep, Wp + O4p, 512);
    }
    { // head_p (mu_p|lp interleaved) + KL accumulate: N=512, K=256
        ADesc ad{}; ad.s[0] = HZPsq;
        EP_PHEAD ep{bpm, bps, MUQ, LQ, outKL};
        tgemm<128><<<dim3(4, BT / 64), blk, SMEM128>>>(ad, ep, Wp + O5p, 256);
    }

    // phase 3b: g = tanh([x|h|z] @ Wg + bg), N=128, K=768
    {
        ADesc ad{}; ad.s[0] = Xs; ad.s[1] = Hseq; ad.s[2] = Zseq;
        EP_G ep{Gb, bg};
        tgemm<128><<<dim3(1, BT / 64), blk, SMEM128>>>(ad, ep, Wp + O6, 768);
    }
    yhead<<<BT / 8, 256>>>(Gb, Wy, by, outY);
    gatherGT<<<Bn, Gn>>>(Gb, Tph, outGT);
}